// round 6
// baseline (speedup 1.0000x reference)
#include <cuda_runtime.h>
#include <math.h>

#define T_TOK 1024
#define DDIM  1024
#define FDIM  2048
#define NEXP  16

#define BM   128
#define BK   32
#define BN1  32            // gemm1 N tile
#define BN2  64            // gemm2 N tile
#define ASTR 36            // BK+4 floats; conflict-free A reads
#define BSTR1 40           // BN1+8
#define BSTR2 72           // BN2+8
#define S1 3
#define S2 4
#define ASZ  (BM * ASTR)   // 4608 floats / stage
#define BSZ1 (BK * BSTR1)  // 1280
#define BSZ2 (BK * BSTR2)  // 2304
#define KSPLIT 2
#define KCH (FDIM / KSPLIT)  // 1024

#define SMEM1 (S1 * (ASZ + 2 * BSZ1) * 4)  // 86016 B
#define SMEM2 (S2 * (ASZ + BSZ2) * 4)      // 110592 B

// ---- device scratch (no allocations allowed) ----
__device__ __align__(16) int   g_cnt[NEXP];
__device__ __align__(16) int   g_lst[NEXP * T_TOK];     // entries: token*2 + slot
__device__ __align__(16) float g_wt[2 * T_TOK];         // renormalized top-2 weights
__device__ __align__(256) float g_xr[T_TOK * DDIM];     // x pre-rounded to tf32
__device__ __align__(256) float g_h[2 * T_TOK * FDIM];  // 16 MB: silu(g)*u (tf32-rounded)

// ---------------------------------------------------------------- helpers
__device__ __forceinline__ unsigned cvt_tf32(float x) {
    unsigned r;
    asm("cvt.rna.tf32.f32 %0, %1;" : "=r"(r) : "f"(x));
    return r;
}
__device__ __forceinline__ void cpa16(void* smem, const void* g) {
    unsigned s = (unsigned)__cvta_generic_to_shared(smem);
    asm volatile("cp.async.cg.shared.global [%0], [%1], 16;" :: "r"(s), "l"(g));
}
__device__ __forceinline__ void cpa_commit() { asm volatile("cp.async.commit_group;"); }
__device__ __forceinline__ void cpa_wait(int) {}
__device__ __forceinline__ void cpa_wait_g1() { asm volatile("cp.async.wait_group %0;" :: "n"(S1 - 1)); }
__device__ __forceinline__ void cpa_wait_g2() { asm volatile("cp.async.wait_group %0;" :: "n"(S2 - 1)); }

__device__ __forceinline__ void red2(float* p, float a, float b) {
    asm volatile("red.global.add.v2.f32 [%0], {%1,%2};" :: "l"(p), "f"(a), "f"(b) : "memory");
}

__device__ __forceinline__ void mma_tf32(float& c0, float& c1, float& c2, float& c3,
                                         unsigned a0, unsigned a1, unsigned a2, unsigned a3,
                                         unsigned b0, unsigned b1) {
    asm volatile(
        "mma.sync.aligned.m16n8k8.row.col.f32.tf32.tf32.f32 "
        "{%0,%1,%2,%3},{%4,%5,%6,%7},{%8,%9},{%0,%1,%2,%3};"
        : "+f"(c0), "+f"(c1), "+f"(c2), "+f"(c3)
        : "r"(a0), "r"(a1), "r"(a2), "r"(a3), "r"(b0), "r"(b1));
}

// ---------------------------------------------------------------- init (+ pre-round x)
__global__ void init_kernel(float* __restrict__ out, const float* __restrict__ x) {
    int i = blockIdx.x * blockDim.x + threadIdx.x;
    if (i < T_TOK * DDIM) {
        out[i] = 0.0f;
        g_xr[i] = __uint_as_float(cvt_tf32(x[i]));
    }
    if (i < NEXP) g_cnt[i] = 0;
}

// ---------------------------------------------------------------- router (warp per token)
__global__ void router_kernel(const float* __restrict__ x, const float* __restrict__ rw) {
    int warp = (blockIdx.x * blockDim.x + threadIdx.x) >> 5;
    int lane = threadIdx.x & 31;
    if (warp >= T_TOK) return;
    const float* xr = x + (size_t)warp * DDIM;

    float acc[NEXP];
#pragma unroll
    for (int e = 0; e < NEXP; e++) acc[e] = 0.0f;

    for (int d = lane; d < DDIM; d += 32) {
        float xv = xr[d];
        const float* rwr = rw + (size_t)d * NEXP;
#pragma unroll
        for (int e = 0; e < NEXP; e++) acc[e] += xv * rwr[e];
    }
#pragma unroll
    for (int e = 0; e < NEXP; e++)
#pragma unroll
        for (int off = 16; off > 0; off >>= 1)
            acc[e] += __shfl_down_sync(0xFFFFFFFFu, acc[e], off);

    if (lane == 0) {
        int e0 = 0; float l0 = acc[0];
#pragma unroll
        for (int e = 1; e < NEXP; e++)
            if (acc[e] > l0) { l0 = acc[e]; e0 = e; }
        int e1 = -1; float l1 = -3.4e38f;
#pragma unroll
        for (int e = 0; e < NEXP; e++)
            if (e != e0 && acc[e] > l1) { l1 = acc[e]; e1 = e; }
        float t  = expf(l1 - l0);   // softmax normalizer cancels in top-2 renorm
        float w0 = 1.0f / (1.0f + t);
        float w1 = t / (1.0f + t);
        g_wt[2 * warp + 0] = w0;
        g_wt[2 * warp + 1] = w1;
        int p0 = atomicAdd(&g_cnt[e0], 1);
        g_lst[e0 * T_TOK + p0] = warp * 2 + 0;
        int p1 = atomicAdd(&g_cnt[e1], 1);
        g_lst[e1 * T_TOK + p1] = warp * 2 + 1;
    }
}

// ---------------------------------------------------------------- GEMM1: h = silu(X@Wg)*(X@Wu)
// 512 threads, tile 128x32, warp tile 32x8 (4m x 4n warps)
__global__ __launch_bounds__(512, 2) void gemm1_kernel(
    const float* __restrict__ wg, const float* __restrict__ wu) {
    int e = blockIdx.z, mt = blockIdx.y, ft = blockIdx.x;
    int cnt = g_cnt[e];
    if (mt * BM >= cnt) return;

    extern __shared__ float dsm[];
    float* sA = dsm;                 // [S1][BM][ASTR]
    float* sG = dsm + S1 * ASZ;      // [S1][BK][BSTR1]
    float* sU = sG + S1 * BSZ1;      // [S1][BK][BSTR1]
    __shared__ int sIdx[BM];

    int tid = threadIdx.x;
    if (tid < BM) {
        int gi = mt * BM + tid;
        sIdx[tid] = g_lst[e * T_TOK + (gi < cnt ? gi : cnt - 1)];
    }
    __syncthreads();

    // A loader: 128 rows x 2 chunks of 16B each thread (tid>>2 row, tid&3 seg)
    int aRow = tid >> 2, aSeg = tid & 3;
    const float* aP = g_xr + (size_t)(sIdx[aRow] >> 1) * DDIM + aSeg * 4;
    // B loader: threads 0-255 -> wg, 256-511 -> wu. 32 rows x 8 segs.
    int bMat = tid >> 8, bRow = (tid >> 3) & 31, bSeg = tid & 7;
    const float* bGbl = (bMat ? wu : wg) + (size_t)e * DDIM * FDIM
                        + (size_t)bRow * FDIM + ft * BN1 + bSeg * 4;
    float* bSmem = (bMat ? sU : sG) + bRow * BSTR1 + bSeg * 4;

    int lane = tid & 31, warp = tid >> 5;
    int wm = (warp & 3) * 32, wn = (warp >> 2) * 8;
    int qr = lane >> 2, qc = lane & 3;

    float cg[2][4], cu[2][4];
#pragma unroll
    for (int i = 0; i < 2; i++)
#pragma unroll
        for (int k = 0; k < 4; k++) { cg[i][k] = 0.f; cu[i][k] = 0.f; }

    auto prefetch = [&](int k0, int buf) {
        float* a = sA + buf * ASZ + aRow * ASTR + aSeg * 4;
        cpa16(a,      aP + k0);
        cpa16(a + 16, aP + k0 + 16);
        cpa16(bSmem + buf * BSZ1, bGbl + (size_t)k0 * FDIM);
        cpa_commit();
    };

#pragma unroll
    for (int s = 0; s < S1 - 1; s++) prefetch(s * BK, s);

    const int KT = DDIM / BK;  // 32
    for (int kt = 0; kt < KT; kt++) {
        if (kt + S1 - 1 < KT) prefetch((kt + S1 - 1) * BK, (kt + S1 - 1) % S1);
        else cpa_commit();
        cpa_wait_g1();
        __syncthreads();
        int buf = kt % S1;
        const float* aB = sA + buf * ASZ;
        const float* gB = sG + buf * BSZ1;
        const float* uB = sU + buf * BSZ1;
#pragma unroll
        for (int ks = 0; ks < 4; ks++) {
            int k = ks * 8;
            unsigned af[2][4];
#pragma unroll
            for (int mf = 0; mf < 2; mf++) {
                int r = wm + mf * 16 + qr;
                af[mf][0] = __float_as_uint(aB[r * ASTR + k + qc]);
                af[mf][1] = __float_as_uint(aB[(r + 8) * ASTR + k + qc]);
                af[mf][2] = __float_as_uint(aB[r * ASTR + k + qc + 4]);
                af[mf][3] = __float_as_uint(aB[(r + 8) * ASTR + k + qc + 4]);
            }
            int c = wn + qr;
            unsigned bg0 = cvt_tf32(gB[(k + qc) * BSTR1 + c]);
            unsigned bg1 = cvt_tf32(gB[(k + qc + 4) * BSTR1 + c]);
            unsigned bu0 = cvt_tf32(uB[(k + qc) * BSTR1 + c]);
            unsigned bu1 = cvt_tf32(uB[(k + qc + 4) * BSTR1 + c]);
#pragma unroll
            for (int mf = 0; mf < 2; mf++) {
                mma_tf32(cg[mf][0], cg[mf][1], cg[mf][2], cg[mf][3],
                         af[mf][0], af[mf][1], af[mf][2], af[mf][3], bg0, bg1);
                mma_tf32(cu[mf][0], cu[mf][1], cu[mf][2], cu[mf][3],
                         af[mf][0], af[mf][1], af[mf][2], af[mf][3], bu0, bu1);
            }
        }
        __syncthreads();
    }

    // epilogue: h = silu(g)*u, tf32-rounded, float2 stores
#pragma unroll
    for (int mf = 0; mf < 2; mf++)
#pragma unroll
        for (int half = 0; half < 2; half++) {
            int rl = wm + mf * 16 + qr + half * 8;
            int gi = mt * BM + rl;
            if (gi < cnt) {
                int a = sIdx[rl];
                float* hp = g_h + (size_t)a * FDIM + ft * BN1;
                float gv0 = cg[mf][half * 2 + 0], gv1 = cg[mf][half * 2 + 1];
                float uv0 = cu[mf][half * 2 + 0], uv1 = cu[mf][half * 2 + 1];
                float h0 = gv0 / (1.0f + __expf(-gv0)) * uv0;
                float h1 = gv1 / (1.0f + __expf(-gv1)) * uv1;
                int c = wn + qc * 2;
                *reinterpret_cast<float2*>(hp + c) = make_float2(
                    __uint_as_float(cvt_tf32(h0)), __uint_as_float(cvt_tf32(h1)));
            }
        }
}

// ---------------------------------------------------------------- GEMM2: out += w * (h @ Wd)
// 512 threads, tile 128x64, warp tile 32x16 (4m x 4n warps), split-K x2
__global__ __launch_bounds__(512, 2) void gemm2_kernel(
    const float* __restrict__ wd, float* __restrict__ out) {
    int z = blockIdx.z;
    int e = z >> 1, kc = z & 1;
    int mt = blockIdx.y, nt = blockIdx.x;
    int cnt = g_cnt[e];
    if (mt * BM >= cnt) return;

    extern __shared__ float dsm[];
    float* sA = dsm;             // [S2][BM][ASTR]
    float* sB = dsm + S2 * ASZ;  // [S2][BK][BSTR2]
    __shared__ int   sIdx[BM];
    __shared__ float sW[BM];

    int tid = threadIdx.x;
    if (tid < BM) {
        int gi = mt * BM + tid;
        int a = g_lst[e * T_TOK + (gi < cnt ? gi : cnt - 1)];
        sIdx[tid] = a;
        sW[tid] = g_wt[a];
    }
    __syncthreads();

    int aRow = tid >> 2, aSeg = tid & 3;
    const float* aP = g_h + (size_t)sIdx[aRow] * FDIM + kc * KCH + aSeg * 4;
    int bRow = tid >> 4, bSeg = tid & 15;
    const float* bGbl = wd + (size_t)e * FDIM * DDIM + (size_t)(kc * KCH + bRow) * DDIM
                        + nt * BN2 + bSeg * 4;
    float* bSmem = sB + bRow * BSTR2 + bSeg * 4;

    int lane = tid & 31, warp = tid >> 5;
    int wm = (warp & 3) * 32, wn = (warp >> 2) * 16;
    int qr = lane >> 2, qc = lane & 3;

    float cc[2][2][4];
#pragma unroll
    for (int i = 0; i < 2; i++)
#pragma unroll
        for (int j = 0; j < 2; j++)
#pragma unroll
            for (int k = 0; k < 4; k++) cc[i][j][k] = 0.f;

    auto prefetch = [&](int k0, int buf) {
        float* a = sA + buf * ASZ + aRow * ASTR + aSeg * 4;
        cpa16(a,      aP + k0);
        cpa16(a + 16, aP + k0 + 16);
        cpa16(bSmem + buf * BSZ2, bGbl + (size_t)k0 * DDIM);
        cpa_commit();
    };

#pragma unroll
    for (int s = 0; s < S2 - 1; s++) prefetch(s * BK, s);

    const int KT = KCH / BK;  // 32
    for (int kt = 0; kt < KT; kt++) {
        if (kt + S2 - 1 < KT) prefetch((kt + S2 - 1) * BK, (kt + S2 - 1) % S2);
        else cpa_commit();
        cpa_wait_g2();
        __syncthreads();
        int buf = kt % S2;
        const float* aB = sA + buf * ASZ;
        const float* bB = sB + buf * BSZ2;
#pragma unroll
        for (int ks = 0; ks < 4; ks++) {
            int k = ks * 8;
            unsigned af[2][4];
#pragma unroll
            for (int mf = 0; mf < 2; mf++) {
                int r = wm + mf * 16 + qr;
                af[mf][0] = __float_as_uint(aB[r * ASTR + k + qc]);
                af[mf][1] = __float_as_uint(aB[(r + 8) * ASTR + k + qc]);
                af[mf][2] = __float_as_uint(aB[r * ASTR + k + qc + 4]);
                af[mf][3] = __float_as_uint(aB[(r + 8) * ASTR + k + qc + 4]);
            }
#pragma unroll
            for (int nf = 0; nf < 2; nf++) {
                int c = wn + nf * 8 + qr;
                unsigned b0 = cvt_tf32(bB[(k + qc) * BSTR2 + c]);
                unsigned b1 = cvt_tf32(bB[(k + qc + 4) * BSTR2 + c]);
#pragma unroll
                for (int mf = 0; mf < 2; mf++)
                    mma_tf32(cc[mf][nf][0], cc[mf][nf][1], cc[mf][nf][2], cc[mf][nf][3],
                             af[mf][0], af[mf][1], af[mf][2], af[mf][3], b0, b1);
            }
        }
        __syncthreads();
    }

    // epilogue: weighted vector reductions into out
#pragma unroll
    for (int mf = 0; mf < 2; mf++)
#pragma unroll
        for (int half = 0; half < 2; half++) {
            int rl = wm + mf * 16 + qr + half * 8;
            int gi = mt * BM + rl;
            if (gi < cnt) {
                int a = sIdx[rl];
                int tok = a >> 1;
                float w = sW[rl];
                float* op = out + (size_t)tok * DDIM + nt * BN2;
#pragma unroll
                for (int nf = 0; nf < 2; nf++) {
                    int c = wn + nf * 8 + qc * 2;
                    red2(op + c, cc[mf][nf][half * 2 + 0] * w,
                                 cc[mf][nf][half * 2 + 1] * w);
                }
            }
        }
}

// ---------------------------------------------------------------- launch
extern "C" void kernel_launch(void* const* d_in, const int* in_sizes, int n_in,
                              void* d_out, int out_size) {
    const float* x  = (const float*)d_in[0];
    const float* rw = (const float*)d_in[1];
    const float* wg = (const float*)d_in[2];
    const float* wu = (const float*)d_in[3];
    const float* wd = (const float*)d_in[4];
    float* out = (float*)d_out;

    cudaFuncSetAttribute(gemm1_kernel, cudaFuncAttributeMaxDynamicSharedMemorySize, SMEM1);
    cudaFuncSetAttribute(gemm2_kernel, cudaFuncAttributeMaxDynamicSharedMemorySize, SMEM2);

    init_kernel<<<(T_TOK * DDIM + 255) / 256, 256>>>(out, x);
    router_kernel<<<(T_TOK * 32 + 255) / 256, 256>>>(x, rw);

    dim3 g1(FDIM / BN1, T_TOK / BM, NEXP);           // (64, 8, 16) -> 1024 active
    gemm1_kernel<<<g1, 512, SMEM1>>>(wg, wu);

    dim3 g2(DDIM / BN2, T_TOK / BM, NEXP * KSPLIT);  // (16, 8, 32) -> 512 active
    gemm2_kernel<<<g2, 512, SMEM2>>>(wd, out);
}

// round 10
// speedup vs baseline: 1.4896x; 1.4896x over previous
#include <cuda_runtime.h>
#include <math.h>

#define T_TOK 1024
#define DDIM  1024
#define FDIM  2048
#define NEXP  16

#define BM 128
#define BN 64
#define BK 32
#define ASTR 36          // BK+4 floats; conflict-free A fragment reads
#define BSTR 72          // BN+8 floats; conflict-free B fragment reads
#define S1 3             // gemm1 pipeline stages (110.6 KB, 2 CTA/SM)
#define S2 4             // gemm2 pipeline stages (110.6 KB, 2 CTA/SM)
#define ASZ (BM * ASTR)  // 4608 floats / stage
#define BSZ (BK * BSTR)  // 2304 floats / stage
#define KSPLIT 4
#define KCH (FDIM / KSPLIT)  // 512

#define SMEM1 (S1 * (ASZ + 2 * BSZ) * 4)  // 110592 B
#define SMEM2 (S2 * (ASZ + BSZ) * 4)      // 110592 B

// ---- device scratch (no allocations allowed) ----
__device__ __align__(16) int   g_cnt[NEXP];
__device__ __align__(16) int   g_lst[NEXP * T_TOK];     // entries: token*2 + slot
__device__ __align__(16) float g_wt[2 * T_TOK];         // renormalized top-2 weights
__device__ __align__(256) float g_xr[T_TOK * DDIM];     // x pre-rounded to tf32
__device__ __align__(256) float g_h[2 * T_TOK * FDIM];  // 16 MB: silu(g)*u (tf32-rounded)

// ---------------------------------------------------------------- helpers
__device__ __forceinline__ unsigned cvt_tf32(float x) {
    unsigned r;
    asm("cvt.rna.tf32.f32 %0, %1;" : "=r"(r) : "f"(x));
    return r;
}
__device__ __forceinline__ void cpa16(void* smem, const void* g) {
    unsigned s = (unsigned)__cvta_generic_to_shared(smem);
    asm volatile("cp.async.cg.shared.global [%0], [%1], 16;" :: "r"(s), "l"(g));
}
__device__ __forceinline__ void cpa_commit() { asm volatile("cp.async.commit_group;"); }
// prefetch is committed BEFORE these waits -> S+kt groups committed, need commit
// index kt complete -> allow S-1 pending. (R6 bug: reordered prefetch without
// re-deriving this constant.)
__device__ __forceinline__ void cpa_wait_g1() { asm volatile("cp.async.wait_group %0;" :: "n"(S1 - 1)); }
__device__ __forceinline__ void cpa_wait_g2() { asm volatile("cp.async.wait_group %0;" :: "n"(S2 - 1)); }

__device__ __forceinline__ void red2(float* p, float a, float b) {
    asm volatile("red.global.add.v2.f32 [%0], {%1,%2};" :: "l"(p), "f"(a), "f"(b) : "memory");
}

__device__ __forceinline__ void mma_tf32(float& c0, float& c1, float& c2, float& c3,
                                         unsigned a0, unsigned a1, unsigned a2, unsigned a3,
                                         unsigned b0, unsigned b1) {
    asm volatile(
        "mma.sync.aligned.m16n8k8.row.col.f32.tf32.tf32.f32 "
        "{%0,%1,%2,%3},{%4,%5,%6,%7},{%8,%9},{%0,%1,%2,%3};"
        : "+f"(c0), "+f"(c1), "+f"(c2), "+f"(c3)
        : "r"(a0), "r"(a1), "r"(a2), "r"(a3), "r"(b0), "r"(b1));
}

// ---------------------------------------------------------------- init (+ pre-round x)
__global__ void init_kernel(float* __restrict__ out, const float* __restrict__ x) {
    int i = blockIdx.x * blockDim.x + threadIdx.x;
    if (i < T_TOK * DDIM) {
        out[i] = 0.0f;
        g_xr[i] = __uint_as_float(cvt_tf32(x[i]));
    }
    if (i < NEXP) g_cnt[i] = 0;
}

// ---------------------------------------------------------------- router (warp per token)
__global__ void router_kernel(const float* __restrict__ x, const float* __restrict__ rw) {
    int warp = (blockIdx.x * blockDim.x + threadIdx.x) >> 5;
    int lane = threadIdx.x & 31;
    if (warp >= T_TOK) return;
    const float* xr = x + (size_t)warp * DDIM;

    float acc[NEXP];
#pragma unroll
    for (int e = 0; e < NEXP; e++) acc[e] = 0.0f;

    for (int d = lane; d < DDIM; d += 32) {
        float xv = xr[d];
        const float* rwr = rw + (size_t)d * NEXP;
#pragma unroll
        for (int e = 0; e < NEXP; e++) acc[e] += xv * rwr[e];
    }
#pragma unroll
    for (int e = 0; e < NEXP; e++)
#pragma unroll
        for (int off = 16; off > 0; off >>= 1)
            acc[e] += __shfl_down_sync(0xFFFFFFFFu, acc[e], off);

    if (lane == 0) {
        int e0 = 0; float l0 = acc[0];
#pragma unroll
        for (int e = 1; e < NEXP; e++)
            if (acc[e] > l0) { l0 = acc[e]; e0 = e; }
        int e1 = -1; float l1 = -3.4e38f;
#pragma unroll
        for (int e = 0; e < NEXP; e++)
            if (e != e0 && acc[e] > l1) { l1 = acc[e]; e1 = e; }
        float t  = expf(l1 - l0);   // softmax normalizer cancels in top-2 renorm
        float w0 = 1.0f / (1.0f + t);
        float w1 = t / (1.0f + t);
        g_wt[2 * warp + 0] = w0;
        g_wt[2 * warp + 1] = w1;
        int p0 = atomicAdd(&g_cnt[e0], 1);
        g_lst[e0 * T_TOK + p0] = warp * 2 + 0;
        int p1 = atomicAdd(&g_cnt[e1], 1);
        g_lst[e1 * T_TOK + p1] = warp * 2 + 1;
    }
}

// ---------------------------------------------------------------- GEMM1: h = silu(X@Wg)*(X@Wu)
// 256 threads, tile 128x64, warp tile 32x32 (4m x 2n warps)
__global__ __launch_bounds__(256, 1) void gemm1_kernel(
    const float* __restrict__ wg, const float* __restrict__ wu) {
    int e = blockIdx.z, mt = blockIdx.y, ft = blockIdx.x;
    int cnt = g_cnt[e];
    if (mt * BM >= cnt) return;

    extern __shared__ float dsm[];
    float* sA = dsm;                 // [S1][BM][ASTR]
    float* sG = dsm + S1 * ASZ;      // [S1][BK][BSTR]
    float* sU = sG + S1 * BSZ;       // [S1][BK][BSTR]
    __shared__ int sIdx[BM];

    int tid = threadIdx.x;
    if (tid < BM) {
        int gi = mt * BM + tid;
        sIdx[tid] = g_lst[e * T_TOK + (gi < cnt ? gi : cnt - 1)];
    }
    __syncthreads();

    const float* wgE = wg + (size_t)e * DDIM * FDIM + ft * BN;
    const float* wuE = wu + (size_t)e * DDIM * FDIM + ft * BN;

    int aRow = tid >> 3, aSeg = tid & 7;     // 32 rows x 8 segs, x4 -> 128 rows
    int bRow = tid >> 4, bSeg = tid & 15;    // 16 rows x 16 segs, x2 -> 32 rows
    const float* aP[4];
#pragma unroll
    for (int i = 0; i < 4; i++)
        aP[i] = g_xr + (size_t)(sIdx[aRow + i * 32] >> 1) * DDIM + aSeg * 4;

    int lane = tid & 31, warp = tid >> 5;
    int wm = (warp & 3) * 32, wn = (warp >> 2) * 32;
    int qr = lane >> 2, qc = lane & 3;

    float cg[2][4][4], cu[2][4][4];
#pragma unroll
    for (int i = 0; i < 2; i++)
#pragma unroll
        for (int j = 0; j < 4; j++)
#pragma unroll
            for (int k = 0; k < 4; k++) { cg[i][j][k] = 0.f; cu[i][j][k] = 0.f; }

    auto prefetch = [&](int k0, int buf) {
        float* a = sA + buf * ASZ;
#pragma unroll
        for (int i = 0; i < 4; i++)
            cpa16(a + (aRow + i * 32) * ASTR + aSeg * 4, aP[i] + k0);
        float* g = sG + buf * BSZ;
        float* u = sU + buf * BSZ;
#pragma unroll
        for (int i = 0; i < 2; i++) {
            int r = bRow + i * 16;
            cpa16(g + r * BSTR + bSeg * 4, wgE + (size_t)(k0 + r) * FDIM + bSeg * 4);
            cpa16(u + r * BSTR + bSeg * 4, wuE + (size_t)(k0 + r) * FDIM + bSeg * 4);
        }
        cpa_commit();
    };

#pragma unroll
    for (int s = 0; s < S1 - 1; s++) prefetch(s * BK, s);

    const int KT = DDIM / BK;  // 32
    for (int kt = 0; kt < KT; kt++) {
        if (kt + S1 - 1 < KT) prefetch((kt + S1 - 1) * BK, (kt + S1 - 1) % S1);
        else cpa_commit();
        cpa_wait_g1();
        __syncthreads();
        int buf = kt % S1;
        const float* aB = sA + buf * ASZ;
        const float* gB = sG + buf * BSZ;
        const float* uB = sU + buf * BSZ;
#pragma unroll
        for (int ks = 0; ks < 4; ks++) {
            int k = ks * 8;
            unsigned af[2][4];
#pragma unroll
            for (int mf = 0; mf < 2; mf++) {
                int r = wm + mf * 16 + qr;
                af[mf][0] = __float_as_uint(aB[r * ASTR + k + qc]);
                af[mf][1] = __float_as_uint(aB[(r + 8) * ASTR + k + qc]);
                af[mf][2] = __float_as_uint(aB[r * ASTR + k + qc + 4]);
                af[mf][3] = __float_as_uint(aB[(r + 8) * ASTR + k + qc + 4]);
            }
#pragma unroll
            for (int nf = 0; nf < 4; nf++) {
                int c = wn + nf * 8 + qr;
                unsigned bg0 = cvt_tf32(gB[(k + qc) * BSTR + c]);
                unsigned bg1 = cvt_tf32(gB[(k + qc + 4) * BSTR + c]);
                unsigned bu0 = cvt_tf32(uB[(k + qc) * BSTR + c]);
                unsigned bu1 = cvt_tf32(uB[(k + qc + 4) * BSTR + c]);
#pragma unroll
                for (int mf = 0; mf < 2; mf++) {
                    mma_tf32(cg[mf][nf][0], cg[mf][nf][1], cg[mf][nf][2], cg[mf][nf][3],
                             af[mf][0], af[mf][1], af[mf][2], af[mf][3], bg0, bg1);
                    mma_tf32(cu[mf][nf][0], cu[mf][nf][1], cu[mf][nf][2], cu[mf][nf][3],
                             af[mf][0], af[mf][1], af[mf][2], af[mf][3], bu0, bu1);
                }
            }
        }
        __syncthreads();
    }

    // epilogue: h = silu(g)*u, tf32-rounded, float2 stores
#pragma unroll
    for (int mf = 0; mf < 2; mf++)
#pragma unroll
        for (int half = 0; half < 2; half++) {
            int rl = wm + mf * 16 + qr + half * 8;
            int gi = mt * BM + rl;
            if (gi < cnt) {
                int a = sIdx[rl];
                float* hp = g_h + (size_t)a * FDIM + ft * BN;
#pragma unroll
                for (int nf = 0; nf < 4; nf++) {
                    float gv0 = cg[mf][nf][half * 2 + 0], gv1 = cg[mf][nf][half * 2 + 1];
                    float uv0 = cu[mf][nf][half * 2 + 0], uv1 = cu[mf][nf][half * 2 + 1];
                    float h0 = gv0 / (1.0f + __expf(-gv0)) * uv0;
                    float h1 = gv1 / (1.0f + __expf(-gv1)) * uv1;
                    int c = wn + nf * 8 + qc * 2;
                    *reinterpret_cast<float2*>(hp + c) = make_float2(
                        __uint_as_float(cvt_tf32(h0)), __uint_as_float(cvt_tf32(h1)));
                }
            }
        }
}

// ---------------------------------------------------------------- GEMM2: out += w * (h @ Wd)
// 256 threads, tile 128x64, warp tile 32x32, split-K x4
__global__ __launch_bounds__(256, 1) void gemm2_kernel(
    const float* __restrict__ wd, float* __restrict__ out) {
    int z = blockIdx.z;
    int e = z >> 2, kc = z & 3;
    int mt = blockIdx.y, nt = blockIdx.x;
    int cnt = g_cnt[e];
    if (mt * BM >= cnt) return;

    extern __shared__ float dsm[];
    float* sA = dsm;             // [S2][BM][ASTR]
    float* sB = dsm + S2 * ASZ;  // [S2][BK][BSTR]
    __shared__ int   sIdx[BM];
    __shared__ float sW[BM];

    int tid = threadIdx.x;
    if (tid < BM) {
        int gi = mt * BM + tid;
        int a = g_lst[e * T_TOK + (gi < cnt ? gi : cnt - 1)];
        sIdx[tid] = a;
        sW[tid] = g_wt[a];
    }
    __syncthreads();

    const float* wdE = wd + (size_t)e * FDIM * DDIM + (size_t)kc * KCH * DDIM + nt * BN;

    int aRow = tid >> 3, aSeg = tid & 7;
    int bRow = tid >> 4, bSeg = tid & 15;
    const float* aP[4];
#pragma unroll
    for (int i = 0; i < 4; i++)
        aP[i] = g_h + (size_t)sIdx[aRow + i * 32] * FDIM + kc * KCH + aSeg * 4;

    int lane = tid & 31, warp = tid >> 5;
    int wm = (warp & 3) * 32, wn = (warp >> 2) * 32;
    int qr = lane >> 2, qc = lane & 3;

    float cc[2][4][4];
#pragma unroll
    for (int i = 0; i < 2; i++)
#pragma unroll
        for (int j = 0; j < 4; j++)
#pragma unroll
            for (int k = 0; k < 4; k++) cc[i][j][k] = 0.f;

    auto prefetch = [&](int k0, int buf) {
        float* a = sA + buf * ASZ;
#pragma unroll
        for (int i = 0; i < 4; i++)
            cpa16(a + (aRow + i * 32) * ASTR + aSeg * 4, aP[i] + k0);
        float* b = sB + buf * BSZ;
#pragma unroll
        for (int i = 0; i < 2; i++) {
            int r = bRow + i * 16;
            cpa16(b + r * BSTR + bSeg * 4, wdE + (size_t)(k0 + r) * DDIM + bSeg * 4);
        }
        cpa_commit();
    };

#pragma unroll
    for (int s = 0; s < S2 - 1; s++) prefetch(s * BK, s);

    const int KT = KCH / BK;  // 16
    for (int kt = 0; kt < KT; kt++) {
        if (kt + S2 - 1 < KT) prefetch((kt + S2 - 1) * BK, (kt + S2 - 1) % S2);
        else cpa_commit();
        cpa_wait_g2();
        __syncthreads();
        int buf = kt % S2;
        const float* aB = sA + buf * ASZ;
        const float* bB = sB + buf * BSZ;
#pragma unroll
        for (int ks = 0; ks < 4; ks++) {
            int k = ks * 8;
            unsigned af[2][4];
#pragma unroll
            for (int mf = 0; mf < 2; mf++) {
                int r = wm + mf * 16 + qr;
                af[mf][0] = __float_as_uint(aB[r * ASTR + k + qc]);
                af[mf][1] = __float_as_uint(aB[(r + 8) * ASTR + k + qc]);
                af[mf][2] = __float_as_uint(aB[r * ASTR + k + qc + 4]);
                af[mf][3] = __float_as_uint(aB[(r + 8) * ASTR + k + qc + 4]);
            }
#pragma unroll
            for (int nf = 0; nf < 4; nf++) {
                int c = wn + nf * 8 + qr;
                unsigned b0 = cvt_tf32(bB[(k + qc) * BSTR + c]);
                unsigned b1 = cvt_tf32(bB[(k + qc + 4) * BSTR + c]);
#pragma unroll
                for (int mf = 0; mf < 2; mf++)
                    mma_tf32(cc[mf][nf][0], cc[mf][nf][1], cc[mf][nf][2], cc[mf][nf][3],
                             af[mf][0], af[mf][1], af[mf][2], af[mf][3], b0, b1);
            }
        }
        __syncthreads();
    }

    // epilogue: weighted vector reductions (no-return atomics)
#pragma unroll
    for (int mf = 0; mf < 2; mf++)
#pragma unroll
        for (int half = 0; half < 2; half++) {
            int rl = wm + mf * 16 + qr + half * 8;
            int gi = mt * BM + rl;
            if (gi < cnt) {
                int a = sIdx[rl];
                int tok = a >> 1;
                float w = sW[rl];
                float* op = out + (size_t)tok * DDIM + nt * BN;
#pragma unroll
                for (int nf = 0; nf < 4; nf++) {
                    int c = wn + nf * 8 + qc * 2;
                    red2(op + c, cc[mf][nf][half * 2 + 0] * w,
                                 cc[mf][nf][half * 2 + 1] * w);
                }
            }
        }
}

// ---------------------------------------------------------------- launch
extern "C" void kernel_launch(void* const* d_in, const int* in_sizes, int n_in,
                              void* d_out, int out_size) {
    const float* x  = (const float*)d_in[0];
    const float* rw = (const float*)d_in[1];
    const float* wg = (const float*)d_in[2];
    const float* wu = (const float*)d_in[3];
    const float* wd = (const float*)d_in[4];
    float* out = (float*)d_out;

    cudaFuncSetAttribute(gemm1_kernel, cudaFuncAttributeMaxDynamicSharedMemorySize, SMEM1);
    cudaFuncSetAttribute(gemm2_kernel, cudaFuncAttributeMaxDynamicSharedMemorySize, SMEM2);

    init_kernel<<<(T_TOK * DDIM + 255) / 256, 256>>>(out, x);
    router_kernel<<<(T_TOK * 32 + 255) / 256, 256>>>(x, rw);

    dim3 g1(FDIM / BN, T_TOK / BM, NEXP);            // (32, 8, 16)
    gemm1_kernel<<<g1, 256, SMEM1>>>(wg, wu);

    dim3 g2(DDIM / BN, T_TOK / BM, NEXP * KSPLIT);   // (16, 8, 64)
    gemm2_kernel<<<g2, 256, SMEM2>>>(wd, out);
}